// round 12
// baseline (speedup 1.0000x reference)
#include <cuda_runtime.h>
#include <cuda_fp16.h>
#include <cuda_bf16.h>
#include <math.h>

#define NN 100000
#define EE 1600000
#define DIN 128
#define HC  100
#define CH  50
#define BB  64
#define SCAN_NPB 250  // nodes per scan block
#define SCAN_NB  400  // scan blocks
#define WPAD 104      // padded W smem stride (conflict-free B frags)
#define HSP  112      // hs row stride in halves (16B-aligned, head-split layout)
// hs slot layout per row: [0..49]=head0 ch0..49, [50..55]=0, [56..105]=head1 ch50..99, [106..111]=0

// ------------------------- scratch (device globals) --------------------------
__device__ __align__(16) __half g_hsh[(size_t)NN * HSP];  // hs fp16, 22.4 MB
__device__ __align__(16) float g_a_src[NN * 2];
__device__ __align__(16) float g_a_dst[NN * 2];
__device__ __align__(16) float g_v[2 * DIN];              // W_dst @ att_dst
__device__            int   g_deg[NN];
__device__            int   g_off[NN];
__device__            int   g_cur[NN];
__device__            int   g_csr[EE];                    // src ids grouped by dst
__device__            int   g_part[SCAN_NB + 32];
__device__ __align__(16) float g_ysum[BB];
__device__            int   g_cnt[BB];

__device__ __forceinline__ unsigned int packbf2(float lo, float hi) {
    __nv_bfloat162 t = __floats2bfloat162_rn(lo, hi);
    return *(unsigned int*)&t;
}
__device__ __forceinline__ float2 unpackbf2(unsigned int u) {
    __nv_bfloat162 t = *(__nv_bfloat162*)&u;
    return __bfloat1622float2(t);
}

#define MMA_BF16(c, a0, a1, a2, a3, b0, b1)                                  \
    asm volatile("mma.sync.aligned.m16n8k16.row.col.f32.bf16.bf16.f32 "      \
                 "{%0,%1,%2,%3}, {%4,%5,%6,%7}, {%8,%9}, {%0,%1,%2,%3};"     \
                 : "+f"(c[0]), "+f"(c[1]), "+f"(c[2]), "+f"(c[3])            \
                 : "r"(a0), "r"(a1), "r"(a2), "r"(a3), "r"(b0), "r"(b1))

// ------------------------------- kernels -------------------------------------
__global__ void k_zero() {
    int i = blockIdx.x * blockDim.x + threadIdx.x;
    int stride = gridDim.x * blockDim.x;
    for (int j = i; j < NN; j += stride) g_deg[j] = 0;
    if (i < BB) { g_ysum[i] = 0.f; g_cnt[i] = 0; }
}

// v_dst[h][k] = sum_c W_dst[k, h*CH+c] * att_dst[h*CH+c]
__global__ void k_prep(const float* __restrict__ W_dst,
                       const float* __restrict__ att_dst) {
    int t = blockIdx.x * blockDim.x + threadIdx.x;
    if (t >= 2 * DIN) return;
    int h = t / DIN, k = t % DIN;
    float s = 0.f;
    #pragma unroll 10
    for (int c = 0; c < CH; c++)
        s += W_dst[k * HC + h * CH + c] * att_dst[h * CH + c];
    g_v[h * DIN + k] = s;
}

__global__ void k_count(const int* __restrict__ ei) {
    int e = blockIdx.x * blockDim.x + threadIdx.x;
    if (e >= EE) return;
    atomicAdd(&g_deg[ei[EE + e]], 1);
}

// hs = x_s @ W_src via 3-term bf16 m16n8k16 mma + fused a_src epilogue
__global__ void __launch_bounds__(256, 2)
k_gemm(const float* __restrict__ xs, const float* __restrict__ W,
       const float* __restrict__ att_src) {
    extern __shared__ float sh[];
    float* Whi = sh;                   // [64][WPAD]  (bf16x2 as float bits)
    float* Wlo = sh + 64 * WPAD;
    int tid  = threadIdx.x;
    int lane = tid & 31, wid = tid >> 5;
    int g = lane >> 2, tg = lane & 3;

    for (int idx = tid; idx < 64 * WPAD; idx += 256) {
        int kp = idx / WPAD, n = idx % WPAD;
        float w0 = (n < HC) ? W[(2 * kp) * HC + n] : 0.f;
        float w1 = (n < HC) ? W[(2 * kp + 1) * HC + n] : 0.f;
        unsigned int h = packbf2(w0, w1);
        float2 hf = unpackbf2(h);
        Whi[idx] = __uint_as_float(h);
        Wlo[idx] = __uint_as_float(packbf2(w0 - hf.x, w1 - hf.y));
    }
    __syncthreads();

    int r0 = blockIdx.x * 128 + wid * 16 + g;
    int r1 = r0 + 8;
    const float* xr0 = xs + (size_t)min(r0, NN - 1) * DIN;
    const float* xr1 = xs + (size_t)min(r1, NN - 1) * DIN;

    float c[13][4];
    #pragma unroll
    for (int i = 0; i < 13; i++) {
        c[i][0] = 0.f; c[i][1] = 0.f; c[i][2] = 0.f; c[i][3] = 0.f;
    }

    float2 nxa = *(const float2*)(xr0 + 2 * tg);
    float2 nxb = *(const float2*)(xr1 + 2 * tg);
    float2 nxc = *(const float2*)(xr0 + 2 * tg + 8);
    float2 nxd = *(const float2*)(xr1 + 2 * tg + 8);

    #pragma unroll
    for (int ks = 0; ks < 8; ks++) {
        float2 xa = nxa, xb = nxb, xc = nxc, xd = nxd;
        if (ks < 7) {
            int k0 = (ks + 1) * 16;
            nxa = *(const float2*)(xr0 + k0 + 2 * tg);
            nxb = *(const float2*)(xr1 + k0 + 2 * tg);
            nxc = *(const float2*)(xr0 + k0 + 2 * tg + 8);
            nxd = *(const float2*)(xr1 + k0 + 2 * tg + 8);
        }
        unsigned int a0h = packbf2(xa.x, xa.y);
        unsigned int a1h = packbf2(xb.x, xb.y);
        unsigned int a2h = packbf2(xc.x, xc.y);
        unsigned int a3h = packbf2(xd.x, xd.y);
        float2 f0 = unpackbf2(a0h), f1 = unpackbf2(a1h);
        float2 f2 = unpackbf2(a2h), f3 = unpackbf2(a3h);
        unsigned int a0l = packbf2(xa.x - f0.x, xa.y - f0.y);
        unsigned int a1l = packbf2(xb.x - f1.x, xb.y - f1.y);
        unsigned int a2l = packbf2(xc.x - f2.x, xc.y - f2.y);
        unsigned int a3l = packbf2(xd.x - f3.x, xd.y - f3.y);

        const float* bh = Whi + (ks * 8 + tg) * WPAD + g;
        const float* bl = Wlo + (ks * 8 + tg) * WPAD + g;
        #pragma unroll
        for (int i = 0; i < 13; i++) {
            unsigned int b0h = __float_as_uint(bh[i * 8]);
            unsigned int b1h = __float_as_uint(bh[i * 8 + 4 * WPAD]);
            unsigned int b0l = __float_as_uint(bl[i * 8]);
            unsigned int b1l = __float_as_uint(bl[i * 8 + 4 * WPAD]);
            MMA_BF16(c[i], a0h, a1h, a2h, a3h, b0h, b1h);
            MMA_BF16(c[i], a0h, a1h, a2h, a3h, b0l, b1l);
            MMA_BF16(c[i], a0l, a1l, a2l, a3l, b0h, b1h);
        }
    }

    float pa00 = 0.f, pa01 = 0.f, pa10 = 0.f, pa11 = 0.f;  // [row][head]
    #pragma unroll
    for (int i = 0; i < 13; i++) {
        int col0 = i * 8 + 2 * tg;                  // even, 0..102
        int slot = (col0 < CH) ? col0 : col0 + 6;   // head-split mapping
        __half2 h01 = __floats2half2_rn(c[i][0], c[i][1]);
        __half2 h23 = __floats2half2_rn(c[i][2], c[i][3]);
        if (r0 < NN) *(__half2*)(g_hsh + (size_t)r0 * HSP + slot) = h01;
        if (r1 < NN) *(__half2*)(g_hsh + (size_t)r1 * HSP + slot) = h23;
        float av0 = (col0 < HC)     ? att_src[col0]     : 0.f;
        float av1 = (col0 + 1 < HC) ? att_src[col0 + 1] : 0.f;
        float q0 = c[i][0] * av0 + c[i][1] * av1;
        float q1 = c[i][2] * av0 + c[i][3] * av1;
        if (col0 < CH) { pa00 += q0; pa10 += q1; }
        else           { pa01 += q0; pa11 += q1; }
    }
    {
        int zs = (tg < 3) ? (50 + 2 * tg) : 110;
        __half2 z = __floats2half2_rn(0.f, 0.f);
        if (r0 < NN) *(__half2*)(g_hsh + (size_t)r0 * HSP + zs) = z;
        if (r1 < NN) *(__half2*)(g_hsh + (size_t)r1 * HSP + zs) = z;
    }
    #pragma unroll
    for (int o = 1; o < 4; o <<= 1) {
        pa00 += __shfl_xor_sync(0xFFFFFFFFu, pa00, o);
        pa01 += __shfl_xor_sync(0xFFFFFFFFu, pa01, o);
        pa10 += __shfl_xor_sync(0xFFFFFFFFu, pa10, o);
        pa11 += __shfl_xor_sync(0xFFFFFFFFu, pa11, o);
    }
    if (tg == 0) {
        if (r0 < NN) { g_a_src[r0 * 2 + 0] = pa00; g_a_src[r0 * 2 + 1] = pa01; }
        if (r1 < NN) { g_a_src[r1 * 2 + 0] = pa10; g_a_src[r1 * 2 + 1] = pa11; }
    }
}

// a_dst[n,h] = x_t[n] . v_dst[h]   (warp per node)
__global__ void k_attn(const float* __restrict__ xt) {
    int gt   = blockIdx.x * blockDim.x + threadIdx.x;
    int node = gt >> 5;
    int lane = gt & 31;
    if (node >= NN) return;
    const float4* v4 = (const float4*)g_v;
    float4 vd0 = v4[lane];
    float4 vd1 = v4[32 + lane];
    float4 b = ((const float4*)(xt + (size_t)node * DIN))[lane];
    float d0 = b.x*vd0.x + b.y*vd0.y + b.z*vd0.z + b.w*vd0.w;
    float d1 = b.x*vd1.x + b.y*vd1.y + b.z*vd1.z + b.w*vd1.w;
    #pragma unroll
    for (int off = 16; off; off >>= 1) {
        d0 += __shfl_xor_sync(0xFFFFFFFFu, d0, off);
        d1 += __shfl_xor_sync(0xFFFFFFFFu, d1, off);
    }
    if (lane == 0)
        *(float2*)(g_a_dst + node * 2) = make_float2(d0, d1);
}

// ---- multi-block exclusive scan ----
__global__ void k_scan1() {
    __shared__ int wsum[8];
    int tid  = threadIdx.x;
    int node = blockIdx.x * SCAN_NPB + tid;
    int v = (tid < SCAN_NPB && node < NN) ? g_deg[node] : 0;
    int s = v;
    #pragma unroll
    for (int o = 16; o; o >>= 1) s += __shfl_xor_sync(0xFFFFFFFFu, s, o);
    if ((tid & 31) == 0) wsum[tid >> 5] = s;
    __syncthreads();
    if (tid == 0) {
        int t = 0;
        #pragma unroll
        for (int i = 0; i < 8; i++) t += wsum[i];
        g_part[blockIdx.x] = t;
    }
}

__global__ void k_scan2() {
    __shared__ int sh[512];
    int tid = threadIdx.x;
    int v = (tid < SCAN_NB) ? g_part[tid] : 0;
    sh[tid] = v;
    __syncthreads();
    for (int o = 1; o < 512; o <<= 1) {
        int t = (tid >= o) ? sh[tid - o] : 0;
        __syncthreads();
        sh[tid] += t;
        __syncthreads();
    }
    if (tid < SCAN_NB) g_part[tid] = sh[tid] - v;   // exclusive
}

__global__ void k_scan3() {
    __shared__ int wsum[8];
    int tid  = threadIdx.x;
    int lane = tid & 31, w = tid >> 5;
    int node = blockIdx.x * SCAN_NPB + tid;
    int v = (tid < SCAN_NPB && node < NN) ? g_deg[node] : 0;
    int x = v;
    #pragma unroll
    for (int o = 1; o < 32; o <<= 1) {
        int t = __shfl_up_sync(0xFFFFFFFFu, x, o);
        if (lane >= o) x += t;
    }
    if (lane == 31) wsum[w] = x;
    __syncthreads();
    if (tid == 0) {
        int run = 0;
        #pragma unroll
        for (int i = 0; i < 8; i++) { int t = wsum[i]; wsum[i] = run; run += t; }
    }
    __syncthreads();
    int excl = x - v + wsum[w] + g_part[blockIdx.x];
    if (tid < SCAN_NPB && node < NN) { g_off[node] = excl; g_cur[node] = excl; }
}

__global__ void k_fill(const int* __restrict__ ei) {
    int e = blockIdx.x * blockDim.x + threadIdx.x;
    if (e >= EE) return;
    int src = ei[e];
    int dst = ei[EE + e];
    int pos = atomicAdd(&g_cur[dst], 1);
    g_csr[pos] = src;
}

// accumulate 8 fp16 channels with scalar weight
__device__ __forceinline__ void acc8(uint4 p, float w, float* acc) {
    float2 f;
    f = __half22float2(*(__half2*)&p.x);
    acc[0] = fmaf(f.x, w, acc[0]); acc[1] = fmaf(f.y, w, acc[1]);
    f = __half22float2(*(__half2*)&p.y);
    acc[2] = fmaf(f.x, w, acc[2]); acc[3] = fmaf(f.y, w, acc[3]);
    f = __half22float2(*(__half2*)&p.z);
    acc[4] = fmaf(f.x, w, acc[4]); acc[5] = fmaf(f.y, w, acc[5]);
    f = __half22float2(*(__half2*)&p.w);
    acc[6] = fmaf(f.x, w, acc[6]); acc[7] = fmaf(f.y, w, acc[7]);
}

// fused: per-dst softmax (no max pass; logits bounded) + aggregate + epilogue
__global__ void k_aggr(const int* __restrict__ batch,
                       const float* __restrict__ bias,
                       const float* __restrict__ fcw) {
    long long gt = (long long)blockIdx.x * blockDim.x + threadIdx.x;
    int node = (int)(gt >> 5);
    int lane = (int)(gt & 31);
    if (node >= NN) return;

    int deg = g_deg[node];
    int off = g_off[node];
    float2 ad = *(const float2*)(g_a_dst + node * 2);

    int  ll = lane & 15, hw = lane >> 4;
    int  c0 = ll * 8;                 // slot base
    bool act = ll < 14;
    bool h0lane = ll < 7;             // slots < 56 -> head 0
    float acc[8];
    #pragma unroll
    for (int j = 0; j < 8; j++) acc[j] = 0.f;
    float den0 = 0.f, den1 = 0.f;

    for (int base = 0; base < deg; base += 32) {
        int i = base + lane;
        int src = 0; float ex0 = 0.f, ex1 = 0.f;
        if (i < deg) {
            src = g_csr[off + i];
            float2 as = *(const float2*)(g_a_src + src * 2);
            float e0 = as.x + ad.x; e0 = e0 > 0.f ? e0 : 0.2f * e0;
            float e1 = as.y + ad.y; e1 = e1 > 0.f ? e1 : 0.2f * e1;
            ex0 = __expf(e0);      // no max shift: |e| <~12, safe in fp32
            ex1 = __expf(e1);
            den0 += ex0; den1 += ex1;
        }
        int cnt = min(32, deg - base);
        int hc  = (cnt + 1) >> 1;
        int t = 0;
        for (; t + 4 <= hc; t += 4) {      // 4 edges in flight per half-warp
            #pragma unroll
            for (int u = 0; u < 4; u++) {
                int ia = 2 * (t + u) + hw;
                int   sA = __shfl_sync(0xFFFFFFFFu, src, ia);
                float a0 = __shfl_sync(0xFFFFFFFFu, ex0, ia);
                float a1 = __shfl_sync(0xFFFFFFFFu, ex1, ia);
                if (act) {
                    uint4 pA = *(const uint4*)(g_hsh + (size_t)sA * HSP + c0);
                    acc8(pA, h0lane ? a0 : a1, acc);
                }
            }
        }
        for (; t < hc; t++) {
            int ia = 2 * t + hw;
            int   sA = __shfl_sync(0xFFFFFFFFu, src, ia);
            float a0 = __shfl_sync(0xFFFFFFFFu, ex0, ia);
            float a1 = __shfl_sync(0xFFFFFFFFu, ex1, ia);
            if (act) {
                uint4 pA = *(const uint4*)(g_hsh + (size_t)sA * HSP + c0);
                acc8(pA, h0lane ? a0 : a1, acc);
            }
        }
    }
    #pragma unroll
    for (int o = 16; o; o >>= 1) {
        den0 += __shfl_xor_sync(0xFFFFFFFFu, den0, o);
        den1 += __shfl_xor_sync(0xFFFFFFFFu, den1, o);
    }
    #pragma unroll
    for (int j = 0; j < 8; j++)
        acc[j] += __shfl_xor_sync(0xFFFFFFFFu, acc[j], 16);

    float inv = h0lane ? 1.f / (den0 + 1e-16f) : 1.f / (den1 + 1e-16f);
    float s = 0.f;
    if (hw == 0 && act) {
        #pragma unroll
        for (int j = 0; j < 8; j++) {
            int slot = c0 + j;
            bool valid = h0lane ? (slot < CH) : (slot < 106);
            if (valid) {
                int chan = h0lane ? slot : slot - 6;
                float o = acc[j] * inv + bias[chan];
                s += fmaxf(o, 0.f) * fcw[chan];
            }
        }
    }
    #pragma unroll
    for (int o = 16; o; o >>= 1)
        s += __shfl_xor_sync(0xFFFFFFFFu, s, o);
    if (lane == 0) {
        int b = batch[node];
        atomicAdd(&g_ysum[b], s);
        atomicAdd(&g_cnt[b], 1);
    }
}

__global__ void k_final(float* __restrict__ y, const float* __restrict__ fcb) {
    int b = threadIdx.x;
    if (b < BB) y[b] = g_ysum[b] / fmaxf((float)g_cnt[b], 1.f) + fcb[0];
}

// ------------------------------ launcher -------------------------------------
extern "C" void kernel_launch(void* const* d_in, const int* in_sizes, int n_in,
                              void* d_out, int out_size) {
    const float* x_s       = (const float*)d_in[0];
    const float* x_t       = (const float*)d_in[1];
    const int*   edge_idx  = (const int*)d_in[2];
    // d_in[3] = distances (unused)
    const int*   xs_batch  = (const int*)d_in[4];
    // d_in[5] = x_t_batch (unused)
    const float* W_src     = (const float*)d_in[6];
    const float* W_dst     = (const float*)d_in[7];
    const float* att_src   = (const float*)d_in[8];
    const float* att_dst   = (const float*)d_in[9];
    const float* bias_conv = (const float*)d_in[10];
    const float* fc_w      = (const float*)d_in[11];
    const float* fc_b      = (const float*)d_in[12];
    float*       y         = (float*)d_out;

    // lazy one-time host objects (no device memory involved)
    static cudaStream_t s_csr = nullptr, s_att = nullptr;
    static cudaEvent_t  e_fork = nullptr, e_csr = nullptr, e_att = nullptr;
    static bool init_done = false;
    if (!init_done) {
        cudaStreamCreateWithFlags(&s_csr, cudaStreamNonBlocking);
        cudaStreamCreateWithFlags(&s_att, cudaStreamNonBlocking);
        cudaEventCreateWithFlags(&e_fork, cudaEventDisableTiming);
        cudaEventCreateWithFlags(&e_csr,  cudaEventDisableTiming);
        cudaEventCreateWithFlags(&e_att,  cudaEventDisableTiming);
        const int smem_gemm_i = 64 * WPAD * 2 * (int)sizeof(float);
        cudaFuncSetAttribute(k_gemm, cudaFuncAttributeMaxDynamicSharedMemorySize,
                             smem_gemm_i);
        init_done = true;
    }
    const int smem_gemm = 64 * WPAD * 2 * (int)sizeof(float);  // 53248 B

    // main stream: zero, then fork
    k_zero<<<512, 256>>>();
    cudaEventRecord(e_fork, 0);

    // branch A (s_csr): CSR build
    cudaStreamWaitEvent(s_csr, e_fork, 0);
    k_count<<<(EE + 255) / 256, 256, 0, s_csr>>>(edge_idx);
    k_scan1<<<SCAN_NB, 256, 0, s_csr>>>();
    k_scan2<<<1, 512, 0, s_csr>>>();
    k_scan3<<<SCAN_NB, 256, 0, s_csr>>>();
    k_fill<<<(EE + 255) / 256, 256, 0, s_csr>>>(edge_idx);
    cudaEventRecord(e_csr, s_csr);

    // branch B (s_att): prep + a_dst
    cudaStreamWaitEvent(s_att, e_fork, 0);
    k_prep<<<1, 256, 0, s_att>>>(W_dst, att_dst);
    k_attn<<<(NN * 32 + 255) / 256, 256, 0, s_att>>>(x_t);
    cudaEventRecord(e_att, s_att);

    // branch C (main): gemm
    k_gemm<<<(NN + 127) / 128, 256, smem_gemm>>>(x_s, W_src, att_src);

    // join on main, then aggregate + finalize
    cudaStreamWaitEvent(0, e_csr, 0);
    cudaStreamWaitEvent(0, e_att, 0);
    {
        long long tot = (long long)NN * 32;
        int blocks = (int)((tot + 255) / 256);
        k_aggr<<<blocks, 256>>>(xs_batch, bias_conv, fc_w);
    }
    k_final<<<1, 64>>>(y, fc_b);
}

// round 13
// speedup vs baseline: 1.1444x; 1.1444x over previous
#include <cuda_runtime.h>
#include <cuda_fp16.h>
#include <cuda_bf16.h>
#include <math.h>

#define NN 100000
#define EE 1600000
#define DIN 128
#define HC  100
#define CH  50
#define BB  64
#define SCAN_NPB 250  // nodes per scan block
#define SCAN_NB  400  // scan blocks
#define WPAD 104      // padded W smem stride (conflict-free B frags)
#define HSP  112      // hs row stride in halves (16B-aligned, head-split layout)
// hs slot layout per row: [0..49]=head0 ch0..49, [50..55]=0, [56..105]=head1 ch50..99, [106..111]=0

// ------------------------- scratch (device globals) --------------------------
__device__ __align__(16) __half g_hsh[(size_t)NN * HSP];  // hs fp16, 22.4 MB
__device__ __align__(16) float g_a_src[NN * 2];
__device__ __align__(16) float g_a_dst[NN * 2];
__device__ __align__(16) float g_v[2 * DIN];              // W_dst @ att_dst
__device__            int   g_deg[NN];
__device__            int   g_off[NN];
__device__            int   g_cur[NN];
__device__            int   g_csr[EE];                    // src ids grouped by dst
__device__            int   g_part[SCAN_NB + 32];
__device__ __align__(16) float g_ysum[BB];
__device__            int   g_cnt[BB];

__device__ __forceinline__ unsigned int packbf2(float lo, float hi) {
    __nv_bfloat162 t = __floats2bfloat162_rn(lo, hi);
    return *(unsigned int*)&t;
}
__device__ __forceinline__ float2 unpackbf2(unsigned int u) {
    __nv_bfloat162 t = *(__nv_bfloat162*)&u;
    return __bfloat1622float2(t);
}

#define MMA_BF16(c, a0, a1, a2, a3, b0, b1)                                  \
    asm volatile("mma.sync.aligned.m16n8k16.row.col.f32.bf16.bf16.f32 "      \
                 "{%0,%1,%2,%3}, {%4,%5,%6,%7}, {%8,%9}, {%0,%1,%2,%3};"     \
                 : "+f"(c[0]), "+f"(c[1]), "+f"(c[2]), "+f"(c[3])            \
                 : "r"(a0), "r"(a1), "r"(a2), "r"(a3), "r"(b0), "r"(b1))

// ------------------------------- kernels -------------------------------------
// zero scratch + (last block) v_dst[h][k] = sum_c W_dst[k,h*CH+c]*att_dst[h*CH+c]
__global__ void k_zero(const float* __restrict__ W_dst,
                       const float* __restrict__ att_dst) {
    int i = blockIdx.x * blockDim.x + threadIdx.x;
    int stride = gridDim.x * blockDim.x;
    for (int j = i; j < NN; j += stride) g_deg[j] = 0;
    if (i < BB) { g_ysum[i] = 0.f; g_cnt[i] = 0; }
    if (blockIdx.x == gridDim.x - 1) {
        int t = threadIdx.x;
        if (t < 2 * DIN) {
            int h = t / DIN, k = t % DIN;
            float s = 0.f;
            #pragma unroll 10
            for (int c = 0; c < CH; c++)
                s += W_dst[k * HC + h * CH + c] * att_dst[h * CH + c];
            g_v[h * DIN + k] = s;
        }
    }
}

// count degrees: 4 edges per thread (int4)
__global__ void k_count(const int* __restrict__ ei) {
    int t = blockIdx.x * blockDim.x + threadIdx.x;
    if (t * 4 >= EE) return;
    int4 d = ((const int4*)(ei + EE))[t];
    atomicAdd(&g_deg[d.x], 1);
    atomicAdd(&g_deg[d.y], 1);
    atomicAdd(&g_deg[d.z], 1);
    atomicAdd(&g_deg[d.w], 1);
}

// hs = x_s @ W_src via 3-term bf16 m16n8k16 mma + fused a_src epilogue
__global__ void __launch_bounds__(256, 2)
k_gemm(const float* __restrict__ xs, const float* __restrict__ W,
       const float* __restrict__ att_src) {
    extern __shared__ float sh[];
    float* Whi = sh;                   // [64][WPAD]  (bf16x2 as float bits)
    float* Wlo = sh + 64 * WPAD;
    int tid  = threadIdx.x;
    int lane = tid & 31, wid = tid >> 5;
    int g = lane >> 2, tg = lane & 3;

    for (int idx = tid; idx < 64 * WPAD; idx += 256) {
        int kp = idx / WPAD, n = idx % WPAD;
        float w0 = (n < HC) ? W[(2 * kp) * HC + n] : 0.f;
        float w1 = (n < HC) ? W[(2 * kp + 1) * HC + n] : 0.f;
        unsigned int h = packbf2(w0, w1);
        float2 hf = unpackbf2(h);
        Whi[idx] = __uint_as_float(h);
        Wlo[idx] = __uint_as_float(packbf2(w0 - hf.x, w1 - hf.y));
    }
    __syncthreads();

    int r0 = blockIdx.x * 128 + wid * 16 + g;
    int r1 = r0 + 8;
    const float* xr0 = xs + (size_t)min(r0, NN - 1) * DIN;
    const float* xr1 = xs + (size_t)min(r1, NN - 1) * DIN;

    float c[13][4];
    #pragma unroll
    for (int i = 0; i < 13; i++) {
        c[i][0] = 0.f; c[i][1] = 0.f; c[i][2] = 0.f; c[i][3] = 0.f;
    }

    float2 nxa = *(const float2*)(xr0 + 2 * tg);
    float2 nxb = *(const float2*)(xr1 + 2 * tg);
    float2 nxc = *(const float2*)(xr0 + 2 * tg + 8);
    float2 nxd = *(const float2*)(xr1 + 2 * tg + 8);

    #pragma unroll
    for (int ks = 0; ks < 8; ks++) {
        float2 xa = nxa, xb = nxb, xc = nxc, xd = nxd;
        if (ks < 7) {
            int k0 = (ks + 1) * 16;
            nxa = *(const float2*)(xr0 + k0 + 2 * tg);
            nxb = *(const float2*)(xr1 + k0 + 2 * tg);
            nxc = *(const float2*)(xr0 + k0 + 2 * tg + 8);
            nxd = *(const float2*)(xr1 + k0 + 2 * tg + 8);
        }
        unsigned int a0h = packbf2(xa.x, xa.y);
        unsigned int a1h = packbf2(xb.x, xb.y);
        unsigned int a2h = packbf2(xc.x, xc.y);
        unsigned int a3h = packbf2(xd.x, xd.y);
        float2 f0 = unpackbf2(a0h), f1 = unpackbf2(a1h);
        float2 f2 = unpackbf2(a2h), f3 = unpackbf2(a3h);
        unsigned int a0l = packbf2(xa.x - f0.x, xa.y - f0.y);
        unsigned int a1l = packbf2(xb.x - f1.x, xb.y - f1.y);
        unsigned int a2l = packbf2(xc.x - f2.x, xc.y - f2.y);
        unsigned int a3l = packbf2(xd.x - f3.x, xd.y - f3.y);

        const float* bh = Whi + (ks * 8 + tg) * WPAD + g;
        const float* bl = Wlo + (ks * 8 + tg) * WPAD + g;
        #pragma unroll
        for (int i = 0; i < 13; i++) {
            unsigned int b0h = __float_as_uint(bh[i * 8]);
            unsigned int b1h = __float_as_uint(bh[i * 8 + 4 * WPAD]);
            unsigned int b0l = __float_as_uint(bl[i * 8]);
            unsigned int b1l = __float_as_uint(bl[i * 8 + 4 * WPAD]);
            MMA_BF16(c[i], a0h, a1h, a2h, a3h, b0h, b1h);
            MMA_BF16(c[i], a0h, a1h, a2h, a3h, b0l, b1l);
            MMA_BF16(c[i], a0l, a1l, a2l, a3l, b0h, b1h);
        }
    }

    float pa00 = 0.f, pa01 = 0.f, pa10 = 0.f, pa11 = 0.f;  // [row][head]
    #pragma unroll
    for (int i = 0; i < 13; i++) {
        int col0 = i * 8 + 2 * tg;                  // even, 0..102
        int slot = (col0 < CH) ? col0 : col0 + 6;   // head-split mapping
        __half2 h01 = __floats2half2_rn(c[i][0], c[i][1]);
        __half2 h23 = __floats2half2_rn(c[i][2], c[i][3]);
        if (r0 < NN) *(__half2*)(g_hsh + (size_t)r0 * HSP + slot) = h01;
        if (r1 < NN) *(__half2*)(g_hsh + (size_t)r1 * HSP + slot) = h23;
        float av0 = (col0 < HC)     ? att_src[col0]     : 0.f;
        float av1 = (col0 + 1 < HC) ? att_src[col0 + 1] : 0.f;
        float q0 = c[i][0] * av0 + c[i][1] * av1;
        float q1 = c[i][2] * av0 + c[i][3] * av1;
        if (col0 < CH) { pa00 += q0; pa10 += q1; }
        else           { pa01 += q0; pa11 += q1; }
    }
    {
        int zs = (tg < 3) ? (50 + 2 * tg) : 110;
        __half2 z = __floats2half2_rn(0.f, 0.f);
        if (r0 < NN) *(__half2*)(g_hsh + (size_t)r0 * HSP + zs) = z;
        if (r1 < NN) *(__half2*)(g_hsh + (size_t)r1 * HSP + zs) = z;
    }
    #pragma unroll
    for (int o = 1; o < 4; o <<= 1) {
        pa00 += __shfl_xor_sync(0xFFFFFFFFu, pa00, o);
        pa01 += __shfl_xor_sync(0xFFFFFFFFu, pa01, o);
        pa10 += __shfl_xor_sync(0xFFFFFFFFu, pa10, o);
        pa11 += __shfl_xor_sync(0xFFFFFFFFu, pa11, o);
    }
    if (tg == 0) {
        if (r0 < NN) { g_a_src[r0 * 2 + 0] = pa00; g_a_src[r0 * 2 + 1] = pa01; }
        if (r1 < NN) { g_a_src[r1 * 2 + 0] = pa10; g_a_src[r1 * 2 + 1] = pa11; }
    }
}

// a_dst[n,h] = x_t[n] . v_dst[h]   (warp per node)
__global__ void k_attn(const float* __restrict__ xt) {
    int gt   = blockIdx.x * blockDim.x + threadIdx.x;
    int node = gt >> 5;
    int lane = gt & 31;
    if (node >= NN) return;
    const float4* v4 = (const float4*)g_v;
    float4 vd0 = v4[lane];
    float4 vd1 = v4[32 + lane];
    float4 b = ((const float4*)(xt + (size_t)node * DIN))[lane];
    float d0 = b.x*vd0.x + b.y*vd0.y + b.z*vd0.z + b.w*vd0.w;
    float d1 = b.x*vd1.x + b.y*vd1.y + b.z*vd1.z + b.w*vd1.w;
    #pragma unroll
    for (int off = 16; off; off >>= 1) {
        d0 += __shfl_xor_sync(0xFFFFFFFFu, d0, off);
        d1 += __shfl_xor_sync(0xFFFFFFFFu, d1, off);
    }
    if (lane == 0)
        *(float2*)(g_a_dst + node * 2) = make_float2(d0, d1);
}

// ---- scan: phase 1 per-block sums -> g_part (raw, unscanned) ----
__global__ void k_scan1() {
    __shared__ int wsum[8];
    int tid  = threadIdx.x;
    int node = blockIdx.x * SCAN_NPB + tid;
    int v = (tid < SCAN_NPB && node < NN) ? g_deg[node] : 0;
    int s = v;
    #pragma unroll
    for (int o = 16; o; o >>= 1) s += __shfl_xor_sync(0xFFFFFFFFu, s, o);
    if ((tid & 31) == 0) wsum[tid >> 5] = s;
    __syncthreads();
    if (tid == 0) {
        int t = 0;
        #pragma unroll
        for (int i = 0; i < 8; i++) t += wsum[i];
        g_part[blockIdx.x] = t;
    }
}

// ---- scan phase 2: per-block base (direct reduce of g_part[0..bid)) + local scan
__global__ void k_scan3() {
    __shared__ int wsum[8];
    __shared__ int sbase;
    int tid  = threadIdx.x;
    int lane = tid & 31, w = tid >> 5;

    // base = sum of g_part[j], j < blockIdx.x
    int b = 0;
    for (int j = tid; j < blockIdx.x; j += 256) b += g_part[j];
    #pragma unroll
    for (int o = 16; o; o >>= 1) b += __shfl_xor_sync(0xFFFFFFFFu, b, o);
    if (lane == 0) wsum[w] = b;
    __syncthreads();
    if (tid == 0) {
        int t = 0;
        #pragma unroll
        for (int i = 0; i < 8; i++) t += wsum[i];
        sbase = t;
    }
    __syncthreads();
    int base = sbase;
    __syncthreads();   // wsum reused below

    int node = blockIdx.x * SCAN_NPB + tid;
    int v = (tid < SCAN_NPB && node < NN) ? g_deg[node] : 0;
    int x = v;
    #pragma unroll
    for (int o = 1; o < 32; o <<= 1) {
        int t = __shfl_up_sync(0xFFFFFFFFu, x, o);
        if (lane >= o) x += t;
    }
    if (lane == 31) wsum[w] = x;
    __syncthreads();
    if (tid == 0) {
        int run = 0;
        #pragma unroll
        for (int i = 0; i < 8; i++) { int t = wsum[i]; wsum[i] = run; run += t; }
    }
    __syncthreads();
    int excl = x - v + wsum[w] + base;
    if (tid < SCAN_NPB && node < NN) { g_off[node] = excl; g_cur[node] = excl; }
}

// fill CSR: 4 edges per thread (int4)
__global__ void k_fill(const int* __restrict__ ei) {
    int t = blockIdx.x * blockDim.x + threadIdx.x;
    if (t * 4 >= EE) return;
    int4 s = ((const int4*)ei)[t];
    int4 d = ((const int4*)(ei + EE))[t];
    g_csr[atomicAdd(&g_cur[d.x], 1)] = s.x;
    g_csr[atomicAdd(&g_cur[d.y], 1)] = s.y;
    g_csr[atomicAdd(&g_cur[d.z], 1)] = s.z;
    g_csr[atomicAdd(&g_cur[d.w], 1)] = s.w;
}

// accumulate 8 fp16 channels with scalar weight
__device__ __forceinline__ void acc8(uint4 p, float w, float* acc) {
    float2 f;
    f = __half22float2(*(__half2*)&p.x);
    acc[0] = fmaf(f.x, w, acc[0]); acc[1] = fmaf(f.y, w, acc[1]);
    f = __half22float2(*(__half2*)&p.y);
    acc[2] = fmaf(f.x, w, acc[2]); acc[3] = fmaf(f.y, w, acc[3]);
    f = __half22float2(*(__half2*)&p.z);
    acc[4] = fmaf(f.x, w, acc[4]); acc[5] = fmaf(f.y, w, acc[5]);
    f = __half22float2(*(__half2*)&p.w);
    acc[6] = fmaf(f.x, w, acc[6]); acc[7] = fmaf(f.y, w, acc[7]);
}

// fused: per-dst softmax (no max pass; logits bounded) + aggregate + epilogue
__global__ void k_aggr(const int* __restrict__ batch,
                       const float* __restrict__ bias,
                       const float* __restrict__ fcw) {
    long long gt = (long long)blockIdx.x * blockDim.x + threadIdx.x;
    int node = (int)(gt >> 5);
    int lane = (int)(gt & 31);
    if (node >= NN) return;

    int deg = g_deg[node];
    int off = g_off[node];
    float2 ad = *(const float2*)(g_a_dst + node * 2);

    int  ll = lane & 15, hw = lane >> 4;
    int  c0 = ll * 8;                 // slot base
    bool act = ll < 14;
    bool h0lane = ll < 7;             // slots < 56 -> head 0
    float acc[8];
    #pragma unroll
    for (int j = 0; j < 8; j++) acc[j] = 0.f;
    float den0 = 0.f, den1 = 0.f;

    for (int base = 0; base < deg; base += 32) {
        int i = base + lane;
        int src = 0; float ex0 = 0.f, ex1 = 0.f;
        if (i < deg) {
            src = g_csr[off + i];
            float2 as = *(const float2*)(g_a_src + src * 2);
            float e0 = as.x + ad.x; e0 = e0 > 0.f ? e0 : 0.2f * e0;
            float e1 = as.y + ad.y; e1 = e1 > 0.f ? e1 : 0.2f * e1;
            ex0 = __expf(e0);      // no max shift: |e| <~12, safe in fp32
            ex1 = __expf(e1);
            den0 += ex0; den1 += ex1;
        }
        int cnt = min(32, deg - base);
        int hc  = (cnt + 1) >> 1;
        int t = 0;
        for (; t + 4 <= hc; t += 4) {      // 4 edges in flight per half-warp
            #pragma unroll
            for (int u = 0; u < 4; u++) {
                int ia = 2 * (t + u) + hw;
                int   sA = __shfl_sync(0xFFFFFFFFu, src, ia);
                float a0 = __shfl_sync(0xFFFFFFFFu, ex0, ia);
                float a1 = __shfl_sync(0xFFFFFFFFu, ex1, ia);
                if (act) {
                    uint4 pA = *(const uint4*)(g_hsh + (size_t)sA * HSP + c0);
                    acc8(pA, h0lane ? a0 : a1, acc);
                }
            }
        }
        for (; t < hc; t++) {
            int ia = 2 * t + hw;
            int   sA = __shfl_sync(0xFFFFFFFFu, src, ia);
            float a0 = __shfl_sync(0xFFFFFFFFu, ex0, ia);
            float a1 = __shfl_sync(0xFFFFFFFFu, ex1, ia);
            if (act) {
                uint4 pA = *(const uint4*)(g_hsh + (size_t)sA * HSP + c0);
                acc8(pA, h0lane ? a0 : a1, acc);
            }
        }
    }
    #pragma unroll
    for (int o = 16; o; o >>= 1) {
        den0 += __shfl_xor_sync(0xFFFFFFFFu, den0, o);
        den1 += __shfl_xor_sync(0xFFFFFFFFu, den1, o);
    }
    #pragma unroll
    for (int j = 0; j < 8; j++)
        acc[j] += __shfl_xor_sync(0xFFFFFFFFu, acc[j], 16);

    float inv = h0lane ? 1.f / (den0 + 1e-16f) : 1.f / (den1 + 1e-16f);
    float s = 0.f;
    if (hw == 0 && act) {
        #pragma unroll
        for (int j = 0; j < 8; j++) {
            int slot = c0 + j;
            bool valid = h0lane ? (slot < CH) : (slot < 106);
            if (valid) {
                int chan = h0lane ? slot : slot - 6;
                float o = acc[j] * inv + bias[chan];
                s += fmaxf(o, 0.f) * fcw[chan];
            }
        }
    }
    #pragma unroll
    for (int o = 16; o; o >>= 1)
        s += __shfl_xor_sync(0xFFFFFFFFu, s, o);
    if (lane == 0) {
        int b = batch[node];
        atomicAdd(&g_ysum[b], s);
        atomicAdd(&g_cnt[b], 1);
    }
}

__global__ void k_final(float* __restrict__ y, const float* __restrict__ fcb) {
    int b = threadIdx.x;
    if (b < BB) y[b] = g_ysum[b] / fmaxf((float)g_cnt[b], 1.f) + fcb[0];
}

// ------------------------------ launcher -------------------------------------
extern "C" void kernel_launch(void* const* d_in, const int* in_sizes, int n_in,
                              void* d_out, int out_size) {
    const float* x_s       = (const float*)d_in[0];
    const float* x_t       = (const float*)d_in[1];
    const int*   edge_idx  = (const int*)d_in[2];
    // d_in[3] = distances (unused)
    const int*   xs_batch  = (const int*)d_in[4];
    // d_in[5] = x_t_batch (unused)
    const float* W_src     = (const float*)d_in[6];
    const float* W_dst     = (const float*)d_in[7];
    const float* att_src   = (const float*)d_in[8];
    const float* att_dst   = (const float*)d_in[9];
    const float* bias_conv = (const float*)d_in[10];
    const float* fc_w      = (const float*)d_in[11];
    const float* fc_b      = (const float*)d_in[12];
    float*       y         = (float*)d_out;

    const int smem_gemm = 64 * WPAD * 2 * (int)sizeof(float);  // 53248 B
    cudaFuncSetAttribute(k_gemm, cudaFuncAttributeMaxDynamicSharedMemorySize, smem_gemm);

    k_zero<<<512, 256>>>(W_dst, att_dst);                              // 1
    k_gemm<<<(NN + 127) / 128, 256, smem_gemm>>>(x_s, W_src, att_src); // 2
    k_attn<<<(NN * 32 + 255) / 256, 256>>>(x_t);                       // 3
    k_count<<<(EE / 4 + 255) / 256, 256>>>(edge_idx);                  // 4: profiled
    k_scan1<<<SCAN_NB, 256>>>();                                       // 5
    k_scan3<<<SCAN_NB, 256>>>();                                       // 6
    k_fill<<<(EE / 4 + 255) / 256, 256>>>(edge_idx);                   // 7
    {
        long long tot = (long long)NN * 32;
        int blocks = (int)((tot + 255) / 256);
        k_aggr<<<blocks, 256>>>(xs_batch, bias_conv, fc_w);            // 8
    }
    k_final<<<1, 64>>>(y, fc_b);                                       // 9
}